// round 4
// baseline (speedup 1.0000x reference)
#include <cuda_runtime.h>

#define N_DIS 25000
#define N_MIR 25000
#define NN    50000
#define EE    600000
#define EMB   128

// ---------------- scratch (static device globals: no allocs allowed) --------
__device__ float g_h  [(size_t)NN * EMB];   // layer-0 embeddings
__device__ float g_h1 [(size_t)NN * EMB];   // layer-1 output
__device__ float g_agg[(size_t)NN * EMB];   // neighbor aggregation buffer
__device__ float g_deg[NN];
__device__ float g_inv[NN];

// ---------------- zero kernels ----------------------------------------------
__global__ void zero_agg_kernel() {
    const int n4 = (NN * EMB) / 4;
    float4 z = make_float4(0.f, 0.f, 0.f, 0.f);
    float4* p = reinterpret_cast<float4*>(g_agg);
    for (int i = blockIdx.x * blockDim.x + threadIdx.x; i < n4;
         i += gridDim.x * blockDim.x)
        p[i] = z;
}

__global__ void zero_deg_kernel() {
    int i = blockIdx.x * blockDim.x + threadIdx.x;
    if (i < NN) g_deg[i] = 0.f;
}

// ---------------- degree + inverse degree -----------------------------------
__global__ void deg_kernel(const int* __restrict__ dst) {
    int e = blockIdx.x * blockDim.x + threadIdx.x;
    if (e < EE) atomicAdd(&g_deg[dst[e]], 1.0f);
}

__global__ void inv_kernel() {
    int i = blockIdx.x * blockDim.x + threadIdx.x;
    if (i < NN) g_inv[i] = 1.0f / fmaxf(g_deg[i], 1.0f);
}

// ---------------- scatter-mean: agg[dst] += x[src] * inv_deg[dst] -----------
// One edge per 32-thread group; each lane moves one float4 (128 floats/edge).
// Per edge the 32 lanes cover a contiguous 512B region -> full-sector REDs.
__global__ void scatter_kernel(const float* __restrict__ x,
                               const int*   __restrict__ src,
                               const int*   __restrict__ dst) {
    int gid  = blockIdx.x * blockDim.x + threadIdx.x;
    int e    = gid >> 5;
    int lane = gid & 31;
    if (e >= EE) return;
    int s = src[e];
    int d = dst[e];
    float w = g_inv[d];
    float4 v = reinterpret_cast<const float4*>(x + (size_t)s * EMB)[lane];
    float* out = g_agg + (size_t)d * EMB + lane * 4;
    atomicAdd(out + 0, v.x * w);
    atomicAdd(out + 1, v.y * w);
    atomicAdd(out + 2, v.z * w);
    atomicAdd(out + 3, v.w * w);
}

// ---------------- SGEMM: C = A1@W1 (+ A2@W2) + bias, optional ReLU ----------
// BM=BN=128, BK=16, 256 threads, 8x8 microtile with split 4+4 strips
// (rows {ty*4..+3, ty*4+64..+67}, cols {tx*4..+3, tx*4+64..+67}) so all
// inner-loop shared reads are conflict-free float4 broadcasts.
#define BM 128
#define BN 128
#define BK 16
#define AS_STRIDE 132   // multiple of 4 (float4-aligned rows), 132%32=4

__global__ __launch_bounds__(256, 2)
void gemm_kernel(const float* __restrict__ A1, const float* __restrict__ W1,
                 const float* __restrict__ A2, const float* __restrict__ W2,
                 const float* __restrict__ bias, float* __restrict__ C,
                 int M, int K1, int K2, int do_relu)
{
    __shared__ float As[BK * AS_STRIDE];
    __shared__ float Bs[BK * BN];

    const int t    = threadIdx.x;
    const int row0 = blockIdx.x * BM;
    const int tx   = t & 15;     // 0..15 -> column strips
    const int ty   = t >> 4;     // 0..15 -> row strips

    float acc[8][8];
#pragma unroll
    for (int i = 0; i < 8; ++i)
#pragma unroll
        for (int j = 0; j < 8; ++j) acc[i][j] = 0.f;

    for (int phase = 0; phase < 2; ++phase) {
        const float* A = phase ? A2 : A1;
        const float* W = phase ? W2 : W1;
        const int    K = phase ? K2 : K1;

        for (int k0 = 0; k0 < K; k0 += BK) {
            // --- load A tile: thread t owns k = t&15, rows m = (t>>4)+16*i.
            // Warp = 2 rows x 64B contiguous global reads (coalesced).
            {
                const int ka = t & 15;
                const int ma = t >> 4;
                const int gk = k0 + ka;
                const bool kok = (gk < K);
#pragma unroll
                for (int i = 0; i < 8; ++i) {
                    int m  = ma + 16 * i;
                    int gm = row0 + m;
                    float v = 0.f;
                    if (kok && gm < M) v = A[(size_t)gm * K + gk];
                    As[ka * AS_STRIDE + m] = v;
                }
            }
            // --- load W tile as float4 (fully coalesced, conflict-free store)
            {
                const int c4 = t & 31;
                const int kb = t >> 5;
#pragma unroll
                for (int i = 0; i < 2; ++i) {
                    int k  = kb + 8 * i;
                    int gk = k0 + k;
                    float4 v = make_float4(0.f, 0.f, 0.f, 0.f);
                    if (gk < K)
                        v = reinterpret_cast<const float4*>(W + (size_t)gk * BN)[c4];
                    reinterpret_cast<float4*>(Bs + k * BN)[c4] = v;
                }
            }
            __syncthreads();

#pragma unroll
            for (int k = 0; k < BK; ++k) {
                float4 a0 = *reinterpret_cast<const float4*>(&As[k * AS_STRIDE + ty * 4]);
                float4 a1 = *reinterpret_cast<const float4*>(&As[k * AS_STRIDE + ty * 4 + 64]);
                float4 b0 = *reinterpret_cast<const float4*>(&Bs[k * BN + tx * 4]);
                float4 b1 = *reinterpret_cast<const float4*>(&Bs[k * BN + tx * 4 + 64]);
                float a[8] = {a0.x, a0.y, a0.z, a0.w, a1.x, a1.y, a1.z, a1.w};
                float b[8] = {b0.x, b0.y, b0.z, b0.w, b1.x, b1.y, b1.z, b1.w};
#pragma unroll
                for (int i = 0; i < 8; ++i)
#pragma unroll
                    for (int j = 0; j < 8; ++j)
                        acc[i][j] += a[i] * b[j];
            }
            __syncthreads();
        }
    }

    // --- epilogue: bias (+ReLU), float4 stores per 4-col strip
#pragma unroll
    for (int i = 0; i < 8; ++i) {
        int m  = (i < 4) ? (ty * 4 + i) : (ty * 4 + 64 + (i - 4));
        int gm = row0 + m;
        if (gm >= M) continue;
#pragma unroll
        for (int js = 0; js < 2; ++js) {
            int n0 = tx * 4 + js * 64;
            float4 v;
            float* vp = &v.x;
#pragma unroll
            for (int j = 0; j < 4; ++j) {
                float x = acc[i][js * 4 + j] + bias[n0 + j];
                if (do_relu) x = fmaxf(x, 0.f);
                vp[j] = x;
            }
            *reinterpret_cast<float4*>(C + (size_t)gm * BN + n0) = v;
        }
    }
}

// ---------------- launch ----------------------------------------------------
extern "C" void kernel_launch(void* const* d_in, const int* in_sizes, int n_in,
                              void* d_out, int out_size) {
    const float* d_feat = (const float*)d_in[0];   // [25000, 383]
    const float* m_feat = (const float*)d_in[1];   // [25000, 495]
    const int*   src    = (const int*)  d_in[2];   // [E]
    const int*   dst    = (const int*)  d_in[3];   // [E]
    const float* W_d    = (const float*)d_in[4];   // [383, 128]
    const float* b_d    = (const float*)d_in[5];
    const float* W_m    = (const float*)d_in[6];   // [495, 128]
    const float* b_m    = (const float*)d_in[7];
    const float* W_s1   = (const float*)d_in[8];   // [128, 128]
    const float* W_n1   = (const float*)d_in[9];
    const float* b1     = (const float*)d_in[10];
    const float* W_s2   = (const float*)d_in[11];
    const float* W_n2   = (const float*)d_in[12];
    const float* b2     = (const float*)d_in[13];
    float* out = (float*)d_out;                    // [50000, 128]

    float *h, *h1, *agg;
    cudaGetSymbolAddress((void**)&h,   g_h);
    cudaGetSymbolAddress((void**)&h1,  g_h1);
    cudaGetSymbolAddress((void**)&agg, g_agg);

    const int gemm_threads = 256;
    const int grid_embed = (N_DIS + BM - 1) / BM;   // 196
    const int grid_layer = (NN    + BM - 1) / BM;   // 391
    const int scat_blocks = (EE * 32 + 255) / 256;  // 75000

    // zero deg + agg
    zero_deg_kernel<<<(NN + 255) / 256, 256>>>();
    zero_agg_kernel<<<4096, 256>>>();

    // layer-0 embeddings: h = [d_feat@W_d+b_d ; m_feat@W_m+b_m]
    gemm_kernel<<<grid_embed, gemm_threads>>>(d_feat, W_d, d_feat, W_d, b_d,
                                              h, N_DIS, 383, 0, 0);
    gemm_kernel<<<grid_embed, gemm_threads>>>(m_feat, W_m, m_feat, W_m, b_m,
                                              h + (size_t)N_DIS * EMB, N_MIR, 495, 0, 0);

    // degrees
    deg_kernel<<<(EE + 255) / 256, 256>>>(dst);
    inv_kernel<<<(NN + 255) / 256, 256>>>();

    // layer 1: agg = mean_{src->dst} h ; h1 = relu(h@Ws1 + agg@Wn1 + b1)
    scatter_kernel<<<scat_blocks, 256>>>(h, src, dst);
    gemm_kernel<<<grid_layer, gemm_threads>>>(h, W_s1, agg, W_n1, b1,
                                              h1, NN, 128, 128, 1);

    // layer 2: out = h1@Ws2 + agg2@Wn2 + b2
    zero_agg_kernel<<<4096, 256>>>();
    scatter_kernel<<<scat_blocks, 256>>>(h1, src, dst);
    gemm_kernel<<<grid_layer, gemm_threads>>>(h1, W_s2, agg, W_n2, b2,
                                              out, NN, 128, 128, 0);
}

// round 6
// speedup vs baseline: 1.5137x; 1.5137x over previous
#include <cuda_runtime.h>
#include <cstdint>

#define N_DIS 25000
#define N_MIR 25000
#define NN    50000
#define EE    600000
#define EMB   128

// ---------------- scratch (static device globals: no allocs allowed) --------
__device__ float g_h  [(size_t)NN * EMB];   // layer-0 embeddings
__device__ float g_h1 [(size_t)NN * EMB];   // layer-1 output
__device__ float g_agg[(size_t)NN * EMB];   // neighbor aggregation buffer
__device__ float g_deg[NN];
__device__ float g_inv[NN];

// ---------------- zero kernels ----------------------------------------------
__global__ void zero_agg_kernel() {
    const int n4 = (NN * EMB) / 4;
    float4 z = make_float4(0.f, 0.f, 0.f, 0.f);
    float4* p = reinterpret_cast<float4*>(g_agg);
    for (int i = blockIdx.x * blockDim.x + threadIdx.x; i < n4;
         i += gridDim.x * blockDim.x)
        p[i] = z;
}

__global__ void zero_deg_kernel() {
    int i = blockIdx.x * blockDim.x + threadIdx.x;
    if (i < NN) g_deg[i] = 0.f;
}

// ---------------- degree + inverse degree -----------------------------------
__global__ void deg_kernel(const int* __restrict__ dst) {
    int e = blockIdx.x * blockDim.x + threadIdx.x;
    if (e < EE) atomicAdd(&g_deg[dst[e]], 1.0f);
}

__global__ void inv_kernel() {
    int i = blockIdx.x * blockDim.x + threadIdx.x;
    if (i < NN) g_inv[i] = 1.0f / fmaxf(g_deg[i], 1.0f);
}

// ---------------- scatter-mean: agg[dst] += x[src] * inv_deg[dst] -----------
__global__ void scatter_kernel(const float* __restrict__ x,
                               const int*   __restrict__ src,
                               const int*   __restrict__ dst) {
    int gid  = blockIdx.x * blockDim.x + threadIdx.x;
    int e    = gid >> 5;
    int lane = gid & 31;
    if (e >= EE) return;
    int s = src[e];
    int d = dst[e];
    float w = g_inv[d];
    float4 v = reinterpret_cast<const float4*>(x + (size_t)s * EMB)[lane];
    float* out = g_agg + (size_t)d * EMB + lane * 4;
    atomicAdd(out + 0, v.x * w);
    atomicAdd(out + 1, v.y * w);
    atomicAdd(out + 2, v.z * w);
    atomicAdd(out + 3, v.w * w);
}

// ---------------- TF32 tensor-core GEMM -------------------------------------
// C = A1@W1 (+ A2@W2) + bias, optional ReLU.  N is fixed = 128.
// BM=128, BN=128, BK=32, 256 threads (8 warps). Warp w: rows [ (w&3)*32, +32 ),
// cols [ (w>>2)*64, +64 ) handled as 2 x 8 tiles of m16n8, k in 4 steps of 8.
// Smem strides (As 36, Bs 136) make ALL fragment LDS bank-conflict-free.

__device__ __forceinline__ uint32_t f2tf32(float x) {
    uint32_t r;
    asm("cvt.rna.tf32.f32 %0, %1;\n" : "=r"(r) : "f"(x));
    return r;
}

__device__ __forceinline__ void mma_tf32(float* d, const uint32_t* a,
                                         const uint32_t* b) {
    asm volatile(
        "mma.sync.aligned.m16n8k8.row.col.f32.tf32.tf32.f32 "
        "{%0,%1,%2,%3},{%4,%5,%6,%7},{%8,%9},{%0,%1,%2,%3};\n"
        : "+f"(d[0]), "+f"(d[1]), "+f"(d[2]), "+f"(d[3])
        : "r"(a[0]), "r"(a[1]), "r"(a[2]), "r"(a[3]), "r"(b[0]), "r"(b[1]));
}

#define BM 128
#define BN 128
#define BK 32
#define AST 36    // As row stride (floats): bank(4*g4 + tig + 8*ks) all distinct
#define BST 136   // Bs row stride (floats): bank(8*tig + 8*nt + g4) all distinct

__global__ __launch_bounds__(256, 2)
void gemm_tc(const float* __restrict__ A1, const float* __restrict__ W1,
             const float* __restrict__ A2, const float* __restrict__ W2,
             const float* __restrict__ bias, float* __restrict__ C,
             int M, int K1, int K2, int do_relu)
{
    __shared__ uint32_t As[BM * AST];   // [m][k]
    __shared__ uint32_t Bs[BK * BST];   // [k][n]

    const int t    = threadIdx.x;
    const int lane = t & 31;
    const int warp = t >> 5;
    const int wm   = warp & 3;          // M quadrant (32 rows)
    const int wn   = warp >> 2;         // N half (64 cols)
    const int g4   = lane >> 2;
    const int tig  = lane & 3;
    const int row0 = blockIdx.x * BM;

    float acc[2][8][4];
#pragma unroll
    for (int mt = 0; mt < 2; ++mt)
#pragma unroll
        for (int nt = 0; nt < 8; ++nt)
#pragma unroll
            for (int j = 0; j < 4; ++j) acc[mt][nt][j] = 0.f;

    // loader coordinates
    const int la_m = t >> 5;            // A: row = la_m + 8*i, col = la_k
    const int la_k = lane;
    const int lb_k = t >> 5;            // B: row = lb_k + 8*i, col4 = lb_n4
    const int lb_n4 = lane;

    for (int phase = 0; phase < 2; ++phase) {
        const float* A = phase ? A2 : A1;
        const float* W = phase ? W2 : W1;
        const int    K = phase ? K2 : K1;
        const int    nk = (K + BK - 1) / BK;
        if (nk == 0) continue;

        float  pa[16];
        float4 pb[4];

        // prologue prefetch (tile 0)
        {
            const int k0 = 0;
#pragma unroll
            for (int i = 0; i < 16; ++i) {
                int m = la_m + 8 * ((i & 1) + 2 * (i >> 1)); // just la_m + 8*i
                m = la_m + 8 * i;
                int gm = row0 + m, gk = k0 + la_k;
                pa[i] = (gm < M && gk < K) ? A[(size_t)gm * K + gk] : 0.f;
            }
#pragma unroll
            for (int i = 0; i < 4; ++i) {
                int gk = k0 + lb_k + 8 * i;
                pb[i] = (gk < K)
                    ? reinterpret_cast<const float4*>(W + (size_t)gk * BN)[lb_n4]
                    : make_float4(0.f, 0.f, 0.f, 0.f);
            }
        }

        for (int it = 0; it < nk; ++it) {
            // ---- store prefetched tile to smem (with tf32 rounding)
#pragma unroll
            for (int i = 0; i < 16; ++i)
                As[(la_m + 8 * i) * AST + la_k] = f2tf32(pa[i]);
#pragma unroll
            for (int i = 0; i < 4; ++i) {
                uint4 v;
                v.x = f2tf32(pb[i].x); v.y = f2tf32(pb[i].y);
                v.z = f2tf32(pb[i].z); v.w = f2tf32(pb[i].w);
                reinterpret_cast<uint4*>(&Bs[(lb_k + 8 * i) * BST])[lb_n4] = v;
            }
            __syncthreads();

            // ---- prefetch next tile into registers (overlaps compute)
            if (it + 1 < nk) {
                const int k0 = (it + 1) * BK;
#pragma unroll
                for (int i = 0; i < 16; ++i) {
                    int gm = row0 + la_m + 8 * i, gk = k0 + la_k;
                    pa[i] = (gm < M && gk < K) ? A[(size_t)gm * K + gk] : 0.f;
                }
#pragma unroll
                for (int i = 0; i < 4; ++i) {
                    int gk = k0 + lb_k + 8 * i;
                    pb[i] = (gk < K)
                        ? reinterpret_cast<const float4*>(W + (size_t)gk * BN)[lb_n4]
                        : make_float4(0.f, 0.f, 0.f, 0.f);
                }
            }

            // ---- compute: 4 k-steps of m16n8k8
#pragma unroll
            for (int ks = 0; ks < 4; ++ks) {
                uint32_t af[2][4];
#pragma unroll
                for (int mt = 0; mt < 2; ++mt) {
                    int r = wm * 32 + mt * 16 + g4;
                    int c = ks * 8 + tig;
                    af[mt][0] = As[r * AST + c];
                    af[mt][1] = As[(r + 8) * AST + c];
                    af[mt][2] = As[r * AST + c + 4];
                    af[mt][3] = As[(r + 8) * AST + c + 4];
                }
#pragma unroll
                for (int nt = 0; nt < 8; ++nt) {
                    uint32_t bf[2];
                    int n = wn * 64 + nt * 8 + g4;
                    bf[0] = Bs[(ks * 8 + tig) * BST + n];
                    bf[1] = Bs[(ks * 8 + tig + 4) * BST + n];
                    mma_tf32(acc[0][nt], af[0], bf);
                    mma_tf32(acc[1][nt], af[1], bf);
                }
            }
            __syncthreads();
        }
    }

    // ---- epilogue: bias (+ReLU), float2 stores
#pragma unroll
    for (int mt = 0; mt < 2; ++mt) {
        int r0 = row0 + wm * 32 + mt * 16 + g4;
#pragma unroll
        for (int nt = 0; nt < 8; ++nt) {
            int ccol = wn * 64 + nt * 8 + 2 * tig;
            float b0 = bias[ccol], b1 = bias[ccol + 1];
            float v0 = acc[mt][nt][0] + b0;
            float v1 = acc[mt][nt][1] + b1;
            float v2 = acc[mt][nt][2] + b0;
            float v3 = acc[mt][nt][3] + b1;
            if (do_relu) {
                v0 = fmaxf(v0, 0.f); v1 = fmaxf(v1, 0.f);
                v2 = fmaxf(v2, 0.f); v3 = fmaxf(v3, 0.f);
            }
            if (r0 < M)
                *reinterpret_cast<float2*>(C + (size_t)r0 * BN + ccol) =
                    make_float2(v0, v1);
            if (r0 + 8 < M)
                *reinterpret_cast<float2*>(C + (size_t)(r0 + 8) * BN + ccol) =
                    make_float2(v2, v3);
        }
    }
}

// ---------------- launch ----------------------------------------------------
extern "C" void kernel_launch(void* const* d_in, const int* in_sizes, int n_in,
                              void* d_out, int out_size) {
    const float* d_feat = (const float*)d_in[0];   // [25000, 383]
    const float* m_feat = (const float*)d_in[1];   // [25000, 495]
    const int*   src    = (const int*)  d_in[2];   // [E]
    const int*   dst    = (const int*)  d_in[3];   // [E]
    const float* W_d    = (const float*)d_in[4];   // [383, 128]
    const float* b_d    = (const float*)d_in[5];
    const float* W_m    = (const float*)d_in[6];   // [495, 128]
    const float* b_m    = (const float*)d_in[7];
    const float* W_s1   = (const float*)d_in[8];   // [128, 128]
    const float* W_n1   = (const float*)d_in[9];
    const float* b1     = (const float*)d_in[10];
    const float* W_s2   = (const float*)d_in[11];
    const float* W_n2   = (const float*)d_in[12];
    const float* b2     = (const float*)d_in[13];
    float* out = (float*)d_out;                    // [50000, 128]

    float *h, *h1, *agg;
    cudaGetSymbolAddress((void**)&h,   g_h);
    cudaGetSymbolAddress((void**)&h1,  g_h1);
    cudaGetSymbolAddress((void**)&agg, g_agg);

    const int grid_embed = (N_DIS + BM - 1) / BM;   // 196
    const int grid_layer = (NN    + BM - 1) / BM;   // 391
    const int scat_blocks = (EE * 32 + 255) / 256;  // 75000

    // zero deg + agg
    zero_deg_kernel<<<(NN + 255) / 256, 256>>>();
    zero_agg_kernel<<<4096, 256>>>();

    // layer-0 embeddings: h = [d_feat@W_d+b_d ; m_feat@W_m+b_m]
    gemm_tc<<<grid_embed, 256>>>(d_feat, W_d, d_feat, W_d, b_d,
                                 h, N_DIS, 383, 0, 0);
    gemm_tc<<<grid_embed, 256>>>(m_feat, W_m, m_feat, W_m, b_m,
                                 h + (size_t)N_DIS * EMB, N_MIR, 495, 0, 0);

    // degrees
    deg_kernel<<<(EE + 255) / 256, 256>>>(dst);
    inv_kernel<<<(NN + 255) / 256, 256>>>();

    // layer 1: agg = mean_{src->dst} h ; h1 = relu(h@Ws1 + agg@Wn1 + b1)
    scatter_kernel<<<scat_blocks, 256>>>(h, src, dst);
    gemm_tc<<<grid_layer, 256>>>(h, W_s1, agg, W_n1, b1,
                                 h1, NN, 128, 128, 1);

    // layer 2: out = h1@Ws2 + agg2@Wn2 + b2
    zero_agg_kernel<<<4096, 256>>>();
    scatter_kernel<<<scat_blocks, 256>>>(h1, src, dst);
    gemm_tc<<<grid_layer, 256>>>(h1, W_s2, agg, W_n2, b2,
                                 out, NN, 128, 128, 0);
}

// round 7
// speedup vs baseline: 3.4365x; 2.2703x over previous
#include <cuda_runtime.h>
#include <cstdint>

#define N_DIS 25000
#define N_MIR 25000
#define NN    50000
#define EE    600000
#define EMB   128
#define NB_SCAN 196   // ceil(50000/256)

// ---------------- scratch (static device globals: no allocs allowed) --------
__device__ float g_h   [(size_t)NN * EMB];   // layer-0 embeddings
__device__ float g_h1  [(size_t)NN * EMB];   // layer-1 output
__device__ float g_agg [(size_t)NN * EMB];   // neighbor aggregation buffer
__device__ float g_inv [NN];
__device__ int   g_cnt [NN];
__device__ int   g_off [NN];                 // exclusive CSR offsets
__device__ int   g_cur [NN];                 // fill cursors
__device__ int   g_esrc[EE];                 // dst-sorted src indices
__device__ int   g_bsum[NB_SCAN];

// ---------------- CSR build --------------------------------------------------
__global__ void zero_cnt_kernel() {
    int i = blockIdx.x * blockDim.x + threadIdx.x;
    if (i < NN) g_cnt[i] = 0;
}

__global__ void count_kernel(const int* __restrict__ dst) {
    int e = blockIdx.x * blockDim.x + threadIdx.x;
    if (e < EE) atomicAdd(&g_cnt[dst[e]], 1);
}

// per-block exclusive scan of counts; block totals to g_bsum
__global__ void scan1_kernel() {
    __shared__ int sh[256];
    int t = threadIdx.x;
    int i = blockIdx.x * 256 + t;
    int v = (i < NN) ? g_cnt[i] : 0;
    sh[t] = v;
    __syncthreads();
#pragma unroll
    for (int o = 1; o < 256; o <<= 1) {
        int x = (t >= o) ? sh[t - o] : 0;
        __syncthreads();
        sh[t] += x;
        __syncthreads();
    }
    if (i < NN) g_off[i] = sh[t] - v;          // exclusive within block
    if (t == 255) g_bsum[blockIdx.x] = sh[255];
}

// single-block exclusive scan of the block sums
__global__ void scan2_kernel() {
    __shared__ int sh[256];
    int t = threadIdx.x;
    int v = (t < NB_SCAN) ? g_bsum[t] : 0;
    sh[t] = v;
    __syncthreads();
#pragma unroll
    for (int o = 1; o < 256; o <<= 1) {
        int x = (t >= o) ? sh[t - o] : 0;
        __syncthreads();
        sh[t] += x;
        __syncthreads();
    }
    if (t < NB_SCAN) g_bsum[t] = sh[t] - v;    // exclusive
}

// finalize offsets, cursors, inv_deg
__global__ void scan3_kernel() {
    int i = blockIdx.x * blockDim.x + threadIdx.x;
    if (i >= NN) return;
    int off = g_off[i] + g_bsum[i >> 8];
    g_off[i] = off;
    g_cur[i] = off;
    g_inv[i] = 1.0f / fmaxf((float)g_cnt[i], 1.0f);
}

__global__ void fill_kernel(const int* __restrict__ src,
                            const int* __restrict__ dst) {
    int e = blockIdx.x * blockDim.x + threadIdx.x;
    if (e >= EE) return;
    int d = dst[e];
    int pos = atomicAdd(&g_cur[d], 1);
    g_esrc[pos] = src[e];
}

// ---------------- gather-mean: agg[n] = inv_deg[n] * sum_{e in CSR(n)} x[src]
// One warp per destination node; 4 floats/lane accumulated in registers.
__global__ void gather_kernel(const float* __restrict__ x) {
    int w    = (blockIdx.x * blockDim.x + threadIdx.x) >> 5;
    int lane = threadIdx.x & 31;
    if (w >= NN) return;
    int beg = g_off[w];
    int end = (w == NN - 1) ? EE : g_off[w + 1];

    float4 acc = make_float4(0.f, 0.f, 0.f, 0.f);
    int e = beg;
    for (; e + 1 < end; e += 2) {
        int s0 = g_esrc[e], s1 = g_esrc[e + 1];
        float4 v0 = reinterpret_cast<const float4*>(x + (size_t)s0 * EMB)[lane];
        float4 v1 = reinterpret_cast<const float4*>(x + (size_t)s1 * EMB)[lane];
        acc.x += v0.x + v1.x; acc.y += v0.y + v1.y;
        acc.z += v0.z + v1.z; acc.w += v0.w + v1.w;
    }
    if (e < end) {
        int s = g_esrc[e];
        float4 v = reinterpret_cast<const float4*>(x + (size_t)s * EMB)[lane];
        acc.x += v.x; acc.y += v.y; acc.z += v.z; acc.w += v.w;
    }
    float iv = g_inv[w];
    acc.x *= iv; acc.y *= iv; acc.z *= iv; acc.w *= iv;
    reinterpret_cast<float4*>(g_agg + (size_t)w * EMB)[lane] = acc;
}

// ---------------- TF32 tensor-core GEMM -------------------------------------
// C = A1@W1 (+ A2@W2) + bias, optional ReLU.  N fixed = 128.
__device__ __forceinline__ uint32_t f2tf32(float x) {
    uint32_t r;
    asm("cvt.rna.tf32.f32 %0, %1;\n" : "=r"(r) : "f"(x));
    return r;
}

__device__ __forceinline__ void mma_tf32(float* d, const uint32_t* a,
                                         const uint32_t* b) {
    asm volatile(
        "mma.sync.aligned.m16n8k8.row.col.f32.tf32.tf32.f32 "
        "{%0,%1,%2,%3},{%4,%5,%6,%7},{%8,%9},{%0,%1,%2,%3};\n"
        : "+f"(d[0]), "+f"(d[1]), "+f"(d[2]), "+f"(d[3])
        : "r"(a[0]), "r"(a[1]), "r"(a[2]), "r"(a[3]), "r"(b[0]), "r"(b[1]));
}

#define BM 128
#define BN 128
#define BK 32
#define AST 36
#define BST 136

__global__ __launch_bounds__(256, 2)
void gemm_tc(const float* __restrict__ A1, const float* __restrict__ W1,
             const float* __restrict__ A2, const float* __restrict__ W2,
             const float* __restrict__ bias, float* __restrict__ C,
             int M, int K1, int K2, int do_relu)
{
    __shared__ uint32_t As[BM * AST];   // [m][k]
    __shared__ uint32_t Bs[BK * BST];   // [k][n]

    const int t    = threadIdx.x;
    const int lane = t & 31;
    const int warp = t >> 5;
    const int wm   = warp & 3;
    const int wn   = warp >> 2;
    const int g4   = lane >> 2;
    const int tig  = lane & 3;
    const int row0 = blockIdx.x * BM;

    float acc[2][8][4];
#pragma unroll
    for (int mt = 0; mt < 2; ++mt)
#pragma unroll
        for (int nt = 0; nt < 8; ++nt)
#pragma unroll
            for (int j = 0; j < 4; ++j) acc[mt][nt][j] = 0.f;

    const int la_m  = t >> 5;
    const int la_k  = lane;
    const int lb_k  = t >> 5;
    const int lb_n4 = lane;

    for (int phase = 0; phase < 2; ++phase) {
        const float* A = phase ? A2 : A1;
        const float* W = phase ? W2 : W1;
        const int    K = phase ? K2 : K1;
        const int    nk = (K + BK - 1) / BK;
        if (nk == 0) continue;

        float  pa[16];
        float4 pb[4];

        {
#pragma unroll
            for (int i = 0; i < 16; ++i) {
                int gm = row0 + la_m + 8 * i, gk = la_k;
                pa[i] = (gm < M && gk < K) ? A[(size_t)gm * K + gk] : 0.f;
            }
#pragma unroll
            for (int i = 0; i < 4; ++i) {
                int gk = lb_k + 8 * i;
                pb[i] = (gk < K)
                    ? reinterpret_cast<const float4*>(W + (size_t)gk * BN)[lb_n4]
                    : make_float4(0.f, 0.f, 0.f, 0.f);
            }
        }

        for (int it = 0; it < nk; ++it) {
#pragma unroll
            for (int i = 0; i < 16; ++i)
                As[(la_m + 8 * i) * AST + la_k] = f2tf32(pa[i]);
#pragma unroll
            for (int i = 0; i < 4; ++i) {
                uint4 v;
                v.x = f2tf32(pb[i].x); v.y = f2tf32(pb[i].y);
                v.z = f2tf32(pb[i].z); v.w = f2tf32(pb[i].w);
                reinterpret_cast<uint4*>(&Bs[(lb_k + 8 * i) * BST])[lb_n4] = v;
            }
            __syncthreads();

            if (it + 1 < nk) {
                const int k0 = (it + 1) * BK;
#pragma unroll
                for (int i = 0; i < 16; ++i) {
                    int gm = row0 + la_m + 8 * i, gk = k0 + la_k;
                    pa[i] = (gm < M && gk < K) ? A[(size_t)gm * K + gk] : 0.f;
                }
#pragma unroll
                for (int i = 0; i < 4; ++i) {
                    int gk = k0 + lb_k + 8 * i;
                    pb[i] = (gk < K)
                        ? reinterpret_cast<const float4*>(W + (size_t)gk * BN)[lb_n4]
                        : make_float4(0.f, 0.f, 0.f, 0.f);
                }
            }

#pragma unroll
            for (int ks = 0; ks < 4; ++ks) {
                uint32_t af[2][4];
#pragma unroll
                for (int mt = 0; mt < 2; ++mt) {
                    int r = wm * 32 + mt * 16 + g4;
                    int c = ks * 8 + tig;
                    af[mt][0] = As[r * AST + c];
                    af[mt][1] = As[(r + 8) * AST + c];
                    af[mt][2] = As[r * AST + c + 4];
                    af[mt][3] = As[(r + 8) * AST + c + 4];
                }
#pragma unroll
                for (int nt = 0; nt < 8; ++nt) {
                    uint32_t bf[2];
                    int n = wn * 64 + nt * 8 + g4;
                    bf[0] = Bs[(ks * 8 + tig) * BST + n];
                    bf[1] = Bs[(ks * 8 + tig + 4) * BST + n];
                    mma_tf32(acc[0][nt], af[0], bf);
                    mma_tf32(acc[1][nt], af[1], bf);
                }
            }
            __syncthreads();
        }
    }

#pragma unroll
    for (int mt = 0; mt < 2; ++mt) {
        int r0 = row0 + wm * 32 + mt * 16 + g4;
#pragma unroll
        for (int nt = 0; nt < 8; ++nt) {
            int ccol = wn * 64 + nt * 8 + 2 * tig;
            float b0 = bias[ccol], b1 = bias[ccol + 1];
            float v0 = acc[mt][nt][0] + b0;
            float v1 = acc[mt][nt][1] + b1;
            float v2 = acc[mt][nt][2] + b0;
            float v3 = acc[mt][nt][3] + b1;
            if (do_relu) {
                v0 = fmaxf(v0, 0.f); v1 = fmaxf(v1, 0.f);
                v2 = fmaxf(v2, 0.f); v3 = fmaxf(v3, 0.f);
            }
            if (r0 < M)
                *reinterpret_cast<float2*>(C + (size_t)r0 * BN + ccol) =
                    make_float2(v0, v1);
            if (r0 + 8 < M)
                *reinterpret_cast<float2*>(C + (size_t)(r0 + 8) * BN + ccol) =
                    make_float2(v2, v3);
        }
    }
}

// ---------------- launch ----------------------------------------------------
extern "C" void kernel_launch(void* const* d_in, const int* in_sizes, int n_in,
                              void* d_out, int out_size) {
    const float* d_feat = (const float*)d_in[0];
    const float* m_feat = (const float*)d_in[1];
    const int*   src    = (const int*)  d_in[2];
    const int*   dst    = (const int*)  d_in[3];
    const float* W_d    = (const float*)d_in[4];
    const float* b_d    = (const float*)d_in[5];
    const float* W_m    = (const float*)d_in[6];
    const float* b_m    = (const float*)d_in[7];
    const float* W_s1   = (const float*)d_in[8];
    const float* W_n1   = (const float*)d_in[9];
    const float* b1     = (const float*)d_in[10];
    const float* W_s2   = (const float*)d_in[11];
    const float* W_n2   = (const float*)d_in[12];
    const float* b2     = (const float*)d_in[13];
    float* out = (float*)d_out;

    float *h, *h1, *agg;
    cudaGetSymbolAddress((void**)&h,   g_h);
    cudaGetSymbolAddress((void**)&h1,  g_h1);
    cudaGetSymbolAddress((void**)&agg, g_agg);

    const int grid_embed   = (N_DIS + BM - 1) / BM;           // 196
    const int grid_layer   = (NN    + BM - 1) / BM;           // 391
    const int grid_edges   = (EE + 255) / 256;                // 2344
    const int grid_nodes   = (NN + 255) / 256;                // 196
    const int grid_gather  = (NN * 32 + 255) / 256;           // 6250

    // ---- CSR build (also yields inv_deg)
    zero_cnt_kernel<<<grid_nodes, 256>>>();
    count_kernel<<<grid_edges, 256>>>(dst);
    scan1_kernel<<<NB_SCAN, 256>>>();
    scan2_kernel<<<1, 256>>>();
    scan3_kernel<<<grid_nodes, 256>>>();
    fill_kernel<<<grid_edges, 256>>>(src, dst);

    // ---- layer-0 embeddings
    gemm_tc<<<grid_embed, 256>>>(d_feat, W_d, d_feat, W_d, b_d,
                                 h, N_DIS, 383, 0, 0);
    gemm_tc<<<grid_embed, 256>>>(m_feat, W_m, m_feat, W_m, b_m,
                                 h + (size_t)N_DIS * EMB, N_MIR, 495, 0, 0);

    // ---- layer 1
    gather_kernel<<<grid_gather, 256>>>(h);
    gemm_tc<<<grid_layer, 256>>>(h, W_s1, agg, W_n1, b1,
                                 h1, NN, 128, 128, 1);

    // ---- layer 2
    gather_kernel<<<grid_gather, 256>>>(h1);
    gemm_tc<<<grid_layer, 256>>>(h1, W_s2, agg, W_n2, b2,
                                 out, NN, 128, 128, 0);
}